// round 15
// baseline (speedup 1.0000x reference)
#include <cuda_runtime.h>
#include <cuda_bf16.h>
#include <math.h>

typedef unsigned long long ull;
typedef unsigned int u32;

#define BB 8
#define SS 2048
#define DM 256
#define NH 4
#define DKK 64
#define NROWS (BB*SS)   // 16384

// ---- scratch (static device, no allocations) ----
__device__ float g_qs[BB*NH*SS*DKK];     // pre-scaled by 1/8
__device__ float g_ks[BB*NH*SS*DKK];
__device__ float g_vs[BB*SS*DKK];
__device__ float g_heads[BB*NH*SS*DKK];
#define QKPAIRS (BB*NH*SS*32)            // 2,097,152
__device__ u32 g_qhi[QKPAIRS];
__device__ u32 g_qlo[QKPAIRS];
__device__ u32 g_khi[QKPAIRS];
__device__ u32 g_klo[QKPAIRS];
#define VTP (BB*DKK*(SS/2))              // 524,288
__device__ u32 g_vthi[VTP];
__device__ u32 g_vtlo[VTP];
#define NATTN (NROWS*NH)                 // 65536 attn rows
__device__ float2 g_part[NATTN*16];      // per (row, ktile): (max, expsum)
__device__ float2 g_stats[NATTN];        // per row [bh*SS+s]: (max, 1/sum)

// ---- bf16 helpers ----
__device__ __forceinline__ u32 bf2(float lo, float hi) {
    u32 r; asm("cvt.rn.bf16x2.f32 %0, %1, %2;" : "=r"(r) : "f"(hi), "f"(lo)); return r;
}
__device__ __forceinline__ float bflo(u32 p) { return __uint_as_float(p << 16); }
__device__ __forceinline__ float bfhi(u32 p) { return __uint_as_float(p & 0xffff0000u); }
__device__ __forceinline__ void split2(float2 p, u32& hi, u32& lo) {
    hi = bf2(p.x, p.y);
    lo = bf2(p.x - bflo(hi), p.y - bfhi(hi));
}

// ---- bf16 mma m16n8k16, fp32 accumulate ----
__device__ __forceinline__ void mma_bf(float* c, const u32* a, u32 b0, u32 b1) {
    asm volatile("mma.sync.aligned.m16n8k16.row.col.f32.bf16.bf16.f32 "
        "{%0,%1,%2,%3}, {%4,%5,%6,%7}, {%8,%9}, {%0,%1,%2,%3};"
        : "+f"(c[0]), "+f"(c[1]), "+f"(c[2]), "+f"(c[3])
        : "r"(a[0]), "r"(a[1]), "r"(a[2]), "r"(a[3]), "r"(b0), "r"(b1));
}

// ---- ldmatrix x4 ----
__device__ __forceinline__ void ldsm4(u32* r, u32 addr) {
    asm volatile("ldmatrix.sync.aligned.m8n8.x4.shared.b16 {%0,%1,%2,%3}, [%4];"
        : "=r"(r[0]), "=r"(r[1]), "=r"(r[2]), "=r"(r[3]) : "r"(addr));
}
__device__ __forceinline__ u32 smem_u32(const void* p) {
    return (u32)__cvta_generic_to_shared(p);
}

// =====================================================================
// Kernel 1: projections via bf16 3-pass mma. grid(128, 9), blk 256.
// =====================================================================
#define PJP 36
#define PROJ_SMEM ((2*128*PJP + 2*64*PJP)*4)   // 55,296 B

__global__ __launch_bounds__(256, 2) void proj_kernel(
    const float* __restrict__ qin, const float* __restrict__ kin,
    const float* __restrict__ vin,
    const float* __restrict__ Wq, const float* __restrict__ bq,
    const float* __restrict__ Wk, const float* __restrict__ bk,
    const float* __restrict__ Wv, const float* __restrict__ bv)
{
    extern __shared__ u32 smu[];
    u32* AH = smu;                 // [128][36]
    u32* AL = AH + 128*PJP;        // [128][36]
    u32* WH = AL + 128*PJP;        // [64][36]
    u32* WL = WH + 64*PJP;         // [64][36]

    int p = blockIdx.y;
    const float *A, *W, *bias;
    float scale; float* dst; int h = 0;
    if (p < 4)      { h = p;   A = qin; W = Wq + h*DKK*DM; bias = bq + h*DKK; scale = 0.125f; dst = g_qs; }
    else if (p < 8) { h = p-4; A = kin; W = Wk + h*DKK*DM; bias = bk + h*DKK; scale = 1.0f;   dst = g_ks; }
    else            {          A = vin; W = Wv;            bias = bv;         scale = 1.0f;   dst = g_vs; }

    int row0 = blockIdx.x * 128;
    int tid  = threadIdx.x;
    int w    = tid >> 5;
    int lane = tid & 31;
    int gid  = lane >> 2;
    int tg   = lane & 3;

    u32 ah_base = smem_u32(AH), al_base = smem_u32(AL);
    u32 wh_base = smem_u32(WH), wl_base = smem_u32(WL);
    u32 a_off = ((u32)((lane & 15)*PJP) + (u32)((lane >> 4)*4)) * 4;
    u32 b_off = ((u32)(((lane & 7) + ((lane >> 4) << 3))*PJP) + (u32)(((lane >> 3) & 1)*4)) * 4;

    float acc[8][4];
#pragma unroll
    for (int nt = 0; nt < 8; nt++)
#pragma unroll
        for (int j = 0; j < 4; j++) acc[nt][j] = 0.0f;

    for (int d0 = 0; d0 < DM; d0 += 64) {
        __syncthreads();
#pragma unroll
        for (int i = 0; i < 8; i++) {
            int f4 = tid + i*256;
            int r = f4 >> 4, c = f4 & 15;
            float4 v = *(const float4*)(A + (size_t)(row0 + r)*DM + d0 + c*4);
            u32 h0, l0, h1, l1;
            split2(make_float2(v.x, v.y), h0, l0);
            split2(make_float2(v.z, v.w), h1, l1);
            AH[r*PJP + 2*c]     = h0;
            AH[r*PJP + 2*c + 1] = h1;
            AL[r*PJP + 2*c]     = l0;
            AL[r*PJP + 2*c + 1] = l1;
        }
#pragma unroll
        for (int i = 0; i < 4; i++) {
            int f4 = tid + i*256;
            int e = f4 >> 4, c = f4 & 15;
            float4 v = *(const float4*)(W + (size_t)e*DM + d0 + c*4);
            u32 h0, l0, h1, l1;
            split2(make_float2(v.x, v.y), h0, l0);
            split2(make_float2(v.z, v.w), h1, l1);
            WH[e*PJP + 2*c]     = h0;
            WH[e*PJP + 2*c + 1] = h1;
            WL[e*PJP + 2*c]     = l0;
            WL[e*PJP + 2*c + 1] = l1;
        }
        __syncthreads();

#pragma unroll
        for (int ks = 0; ks < 4; ks++) {
            u32 Ah[4], Al[4];
            u32 aoff = (u32)(w*16*PJP*4) + (u32)(ks*32) + a_off;
            ldsm4(Ah, ah_base + aoff);
            ldsm4(Al, al_base + aoff);
            u32 Bh[4][4], Bl[4][4];
#pragma unroll
            for (int et2 = 0; et2 < 4; et2++) {
                u32 off = (u32)(et2*16*PJP*4) + (u32)(ks*32) + b_off;
                ldsm4(Bh[et2], wh_base + off);
                ldsm4(Bl[et2], wl_base + off);
            }
#pragma unroll
            for (int nt = 0; nt < 8; nt++) {
                u32 b0 = Bh[nt>>1][(nt&1)*2], b1 = Bh[nt>>1][(nt&1)*2 + 1];
                u32 c0 = Bl[nt>>1][(nt&1)*2], c1 = Bl[nt>>1][(nt&1)*2 + 1];
                mma_bf(acc[nt], Ah, b0, b1);
                mma_bf(acc[nt], Ah, c0, c1);
                mma_bf(acc[nt], Al, b0, b1);
            }
        }
    }

    // epilogue: bias + scale, write fp32
    int r0 = row0 + w*16 + gid;
#pragma unroll
    for (int nt = 0; nt < 8; nt++) {
        int e0 = nt*8 + 2*tg;
        float2 bv2 = *(const float2*)&bias[e0];
#pragma unroll
        for (int half = 0; half < 2; half++) {
            int gr = r0 + half*8;
            int bb = gr >> 11;
            int s  = gr & (SS-1);
            size_t base;
            if (p < 8) base = ((size_t)(bb*NH + h)*SS + s)*DKK;
            else       base = (size_t)gr*DKK;
            float o0 = (acc[nt][half*2 + 0] + bv2.x) * scale;
            float o1 = (acc[nt][half*2 + 1] + bv2.y) * scale;
            *(float2*)&dst[base + e0] = make_float2(o0, o1);
        }
    }
}

// =====================================================================
// Kernel 1b/1c: repack to bf16 hi/lo planes.
// =====================================================================
__global__ __launch_bounds__(256) void repack_qk_kernel()
{
    int t = blockIdx.x * 256 + threadIdx.x;
    const float2* src = (const float2*)(blockIdx.y ? g_ks : g_qs);
    u32* dhi = blockIdx.y ? g_khi : g_qhi;
    u32* dlo = blockIdx.y ? g_klo : g_qlo;
    float2 p = src[t];
    u32 hi, lo; split2(p, hi, lo);
    dhi[t] = hi; dlo[t] = lo;
}

__global__ __launch_bounds__(256) void repack_v_kernel()
{
    int t = blockIdx.x * 256 + threadIdx.x;
    int b  = t >> 16;
    int r  = t & 65535;
    int e  = r >> 10;
    int sp = r & 1023;
    float v0 = g_vs[((size_t)b*SS + 2*sp    )*DKK + e];
    float v1 = g_vs[((size_t)b*SS + 2*sp + 1)*DKK + e];
    u32 hi, lo; split2(make_float2(v0, v1), hi, lo);
    g_vthi[t] = hi; g_vtlo[t] = lo;
}

// =====================================================================
// Kernel 2: scores GEMM v4 (round-14 WINNER, unchanged).
//   grid(4 kgroup, 16 qtile, 32 bh), blk 256.
// =====================================================================
#define SCP 36
#define SCORES_SMEM (4*128*SCP*4)

__global__ __launch_bounds__(256, 2) void scores_kernel(float* __restrict__ attn)
{
    extern __shared__ u32 smu[];
    u32* QH = smu;
    u32* QL = QH + 128*SCP;
    u32* KH = QL + 128*SCP;
    u32* KL = KH + 128*SCP;
    float2* spart = (float2*)KH;         // alias on KH (dead after mainloop)

    int bhid = blockIdx.z;
    int b = bhid >> 2, h = bhid & 3;
    int q0 = blockIdx.y * 128;
    int kg = blockIdx.x;                 // 0..3, 4 ktiles each
    int tid  = threadIdx.x;
    int w    = tid >> 5;
    int lane = tid & 31;
    int gid  = lane >> 2;
    int tg   = lane & 3;

    const u32* qhi = g_qhi + (size_t)bhid*SS*32;
    const u32* qlo = g_qlo + (size_t)bhid*SS*32;
    const u32* khi = g_khi + (size_t)bhid*SS*32;
    const u32* klo = g_klo + (size_t)bhid*SS*32;

    // ---- stage Q planes ONCE ----
#pragma unroll
    for (int i = 0; i < 4; i++) {
        int f4 = tid + i*256;
        int r = f4 >> 3, fo = (f4 & 7) * 4;
        *(uint4*)&QH[r*SCP + fo] = *(const uint4*)&qhi[(size_t)(q0 + r)*32 + fo];
        *(uint4*)&QL[r*SCP + fo] = *(const uint4*)&qlo[(size_t)(q0 + r)*32 + fo];
    }

    int wq = w >> 2;   // 0..1 : 64 q rows
    int wk = w & 3;    // 0..3 : 32 k cols

    u32 qh_base = smem_u32(QH), ql_base = smem_u32(QL);
    u32 kh_base = smem_u32(KH), kl_base = smem_u32(KL);
    u32 a_off = ((u32)((lane & 15)*SCP) + (u32)((lane >> 4)*4)) * 4;
    u32 b_off = ((u32)(((lane & 7) + ((lane >> 4) << 3))*SCP) + (u32)(((lane >> 3) & 1)*4)) * 4;

    for (int kt2 = 0; kt2 < 4; kt2++) {
        int ktile = kg*4 + kt2;
        int k0 = ktile * 128;

        __syncthreads();   // Q staged (iter 0) / prior spart reads done
#pragma unroll
        for (int i = 0; i < 4; i++) {
            int f4 = tid + i*256;
            int r = f4 >> 3, fo = (f4 & 7) * 4;
            *(uint4*)&KH[r*SCP + fo] = *(const uint4*)&khi[(size_t)(k0 + r)*32 + fo];
            *(uint4*)&KL[r*SCP + fo] = *(const uint4*)&klo[(size_t)(k0 + r)*32 + fo];
        }
        __syncthreads();

        float acc[4][4][4];
#pragma unroll
        for (int mt = 0; mt < 4; mt++)
#pragma unroll
            for (int nt = 0; nt < 4; nt++)
#pragma unroll
                for (int j = 0; j < 4; j++) acc[mt][nt][j] = 0.0f;

#pragma unroll
        for (int ks = 0; ks < 4; ks++) {
            u32 Bh[2][4], Bl[2][4];
#pragma unroll
            for (int nt2 = 0; nt2 < 2; nt2++) {
                u32 off = (u32)((wk*32 + nt2*16)*SCP*4) + (u32)(ks*32) + b_off;
                ldsm4(Bh[nt2], kh_base + off);
                ldsm4(Bl[nt2], kl_base + off);
            }
#pragma unroll
            for (int mt = 0; mt < 4; mt++) {
                u32 Ah[4], Al[4];
                u32 off = (u32)((wq*64 + mt*16)*SCP*4) + (u32)(ks*32) + a_off;
                ldsm4(Ah, qh_base + off);
                ldsm4(Al, ql_base + off);
#pragma unroll
                for (int nt = 0; nt < 4; nt++) {
                    u32 b0h = Bh[nt>>1][(nt&1)*2], b1h = Bh[nt>>1][(nt&1)*2 + 1];
                    u32 b0l = Bl[nt>>1][(nt&1)*2], b1l = Bl[nt>>1][(nt&1)*2 + 1];
                    mma_bf(acc[mt][nt], Ah, b0h, b1h);
                    mma_bf(acc[mt][nt], Ah, b0l, b1l);
                    mma_bf(acc[mt][nt], Al, b0h, b1h);
                }
            }
        }

        // epilogue A: raw scores -> attn (register scatter, proven fine)
        float* ab = attn + (((size_t)b*SS + q0)*NH + h)*SS + k0;
#pragma unroll
        for (int mt = 0; mt < 4; mt++) {
            int r = wq*64 + mt*16 + gid;
#pragma unroll
            for (int nt = 0; nt < 4; nt++) {
                int c = wk*32 + nt*8 + 2*tg;
                *(float2*)&ab[(size_t)r*NH*SS + c]       = make_float2(acc[mt][nt][0], acc[mt][nt][1]);
                *(float2*)&ab[(size_t)(r + 8)*NH*SS + c] = make_float2(acc[mt][nt][2], acc[mt][nt][3]);
            }
        }

        // epilogue B: per-(row, ktile) softmax partials into spart (on KH)
        __syncthreads();   // KH ldsm reads complete
#pragma unroll
        for (int mt = 0; mt < 4; mt++) {
            float m0 = -1e30f, m1 = -1e30f;
#pragma unroll
            for (int nt = 0; nt < 4; nt++) {
                m0 = fmaxf(m0, fmaxf(acc[mt][nt][0], acc[mt][nt][1]));
                m1 = fmaxf(m1, fmaxf(acc[mt][nt][2], acc[mt][nt][3]));
            }
            float s0 = 0.f, s1 = 0.f;
#pragma unroll
            for (int nt = 0; nt < 4; nt++) {
                s0 += __expf(acc[mt][nt][0] - m0) + __expf(acc[mt][nt][1] - m0);
                s1 += __expf(acc[mt][nt][2] - m1) + __expf(acc[mt][nt][3] - m1);
            }
#pragma unroll
            for (int off = 1; off <= 2; off <<= 1) {
                float mo0 = __shfl_xor_sync(0xffffffffu, m0, off);
                float so0 = __shfl_xor_sync(0xffffffffu, s0, off);
                float mo1 = __shfl_xor_sync(0xffffffffu, m1, off);
                float so1 = __shfl_xor_sync(0xffffffffu, s1, off);
                float nm0 = fmaxf(m0, mo0);
                s0 = s0*__expf(m0 - nm0) + so0*__expf(mo0 - nm0); m0 = nm0;
                float nm1 = fmaxf(m1, mo1);
                s1 = s1*__expf(m1 - nm1) + so1*__expf(mo1 - nm1); m1 = nm1;
            }
            if (tg == 0) {
                int r0 = wq*64 + mt*16 + gid;
                spart[r0*4 + wk]       = make_float2(m0, s0);
                spart[(r0 + 8)*4 + wk] = make_float2(m1, s1);
            }
        }
        __syncthreads();
        if (tid < 128) {
            float2 p0 = spart[tid*4 + 0];
            float2 p1 = spart[tid*4 + 1];
            float2 p2 = spart[tid*4 + 2];
            float2 p3 = spart[tid*4 + 3];
            float m = fmaxf(fmaxf(p0.x, p1.x), fmaxf(p2.x, p3.x));
            float s = p0.y*__expf(p0.x - m) + p1.y*__expf(p1.x - m)
                    + p2.y*__expf(p2.x - m) + p3.y*__expf(p3.x - m);
            g_part[((size_t)bhid*SS + q0 + tid)*16 + ktile] = make_float2(m, s);
        }
    }
}

// =====================================================================
// Kernel 3: merge partials -> g_stats. grid(1024), blk 256, smem-staged.
// =====================================================================
__global__ __launch_bounds__(256) void merge_kernel()
{
    __shared__ float2 sp[64*16];
    int tid = threadIdx.x;
    const uint4* src = (const uint4*)(g_part + (size_t)blockIdx.x*64*16);
    uint4* d = (uint4*)sp;
    d[tid]       = src[tid];
    d[tid + 256] = src[tid + 256];
    __syncthreads();
    if (tid < 64) {
        const float2* p = &sp[tid*16];
        float m = -1e30f;
#pragma unroll
        for (int i = 0; i < 16; i++) m = fmaxf(m, p[i].x);
        float s = 0.f;
#pragma unroll
        for (int i = 0; i < 16; i++) s += p[i].y * __expf(p[i].x - m);
        g_stats[blockIdx.x*64 + tid] = make_float2(m, 1.0f / s);
    }
}

// =====================================================================
// Kernel 4: PV v4 — 2 q-tiles per CTA (grid 8x32 = 256 CTAs, 1 wave).
//   V staged + V fragments shared across both q-tiles; P path identical
//   to the proven round-8 scattered form. blk 256.
// =====================================================================
#define VDP 68
#define PV_SMEM (2*64*VDP*4)

__global__ __launch_bounds__(256, 2) void pv_kernel(float* __restrict__ attn)
{
    extern __shared__ u32 smu[];
    u32* VH = smu;
    u32* VL = VH + 64*VDP;

    int bhid = blockIdx.y;
    int b = bhid >> 2, h = bhid & 3;
    int q0 = blockIdx.x * 256;           // two q-tiles: q0, q0+128
    int tid  = threadIdx.x;
    int w    = tid >> 5;
    int lane = tid & 31;
    int gid  = lane >> 2;
    int tg   = lane & 3;

    const u32* vh = g_vthi + (size_t)b*DKK*1024;
    const u32* vl = g_vtlo + (size_t)b*DKK*1024;

    int qa = q0 + w*16 + gid;
    float2 st00 = g_stats[(size_t)bhid*SS + qa];
    float2 st01 = g_stats[(size_t)bhid*SS + qa + 8];
    float2 st10 = g_stats[(size_t)bhid*SS + qa + 128];
    float2 st11 = g_stats[(size_t)bhid*SS + qa + 136];

    float* rlo0 = attn + (((size_t)b*SS + qa      )*NH + h)*SS;
    float* rhi0 = attn + (((size_t)b*SS + qa + 8  )*NH + h)*SS;
    float* rlo1 = attn + (((size_t)b*SS + qa + 128)*NH + h)*SS;
    float* rhi1 = attn + (((size_t)b*SS + qa + 136)*NH + h)*SS;

    u32 vh_base = smem_u32(VH), vl_base = smem_u32(VL);
    u32 vb_off = ((u32)(((lane & 7) + ((lane >> 4) << 3))*VDP) + (u32)(((lane >> 3) & 1)*4)) * 4;

    float acc[2][8][4];
#pragma unroll
    for (int qt = 0; qt < 2; qt++)
#pragma unroll
        for (int nt = 0; nt < 8; nt++)
#pragma unroll
            for (int j = 0; j < 4; j++) acc[qt][nt][j] = 0.0f;

    for (int kt = 0; kt < 16; kt++) {
        int k0 = kt * 128;
        __syncthreads();
#pragma unroll
        for (int i = 0; i < 4; i++) {
            int f4 = tid + i*256;
            int e = f4 >> 4, fo = (f4 & 15) * 4;
            *(uint4*)&VH[e*VDP + fo] = *(const uint4*)&vh[(size_t)e*1024 + k0/2 + fo];
            *(uint4*)&VL[e*VDP + fo] = *(const uint4*)&vl[(size_t)e*1024 + k0/2 + fo];
        }
        __syncthreads();

#pragma unroll
        for (int ks = 0; ks < 8; ks++) {
            int c = k0 + ks*16 + 2*tg;
            // ---- P fragments for both q-tiles (loads batched for MLP) ----
            float2 a00 = *(float2*)&rlo0[c];
            float2 a10 = *(float2*)&rhi0[c];
            float2 a01 = *(float2*)&rlo0[c + 8];
            float2 a11 = *(float2*)&rhi0[c + 8];
            float2 b00 = *(float2*)&rlo1[c];
            float2 b10 = *(float2*)&rhi1[c];
            float2 b01 = *(float2*)&rlo1[c + 8];
            float2 b11 = *(float2*)&rhi1[c + 8];
            a00.x = __expf(a00.x - st00.x) * st00.y;  a00.y = __expf(a00.y - st00.x) * st00.y;
            a10.x = __expf(a10.x - st01.x) * st01.y;  a10.y = __expf(a10.y - st01.x) * st01.y;
            a01.x = __expf(a01.x - st00.x) * st00.y;  a01.y = __expf(a01.y - st00.x) * st00.y;
            a11.x = __expf(a11.x - st01.x) * st01.y;  a11.y = __expf(a11.y - st01.x) * st01.y;
            b00.x = __expf(b00.x - st10.x) * st10.y;  b00.y = __expf(b00.y - st10.x) * st10.y;
            b10.x = __expf(b10.x - st11.x) * st11.y;  b10.y = __expf(b10.y - st11.x) * st11.y;
            b01.x = __expf(b01.x - st10.x) * st10.y;  b01.y = __expf(b01.y - st10.x) * st10.y;
            b11.x = __expf(b11.x - st11.x) * st11.y;  b11.y = __expf(b11.y - st11.x) * st11.y;
            *(float2*)&rlo0[c]     = a00;  *(float2*)&rhi0[c]     = a10;
            *(float2*)&rlo0[c + 8] = a01;  *(float2*)&rhi0[c + 8] = a11;
            *(float2*)&rlo1[c]     = b00;  *(float2*)&rhi1[c]     = b10;
            *(float2*)&rlo1[c + 8] = b01;  *(float2*)&rhi1[c + 8] = b11;
            u32 ah[4], al[4], bh_[4], bl_[4];
            split2(a00, ah[0], al[0]);
            split2(a10, ah[1], al[1]);
            split2(a01, ah[2], al[2]);
            split2(a11, ah[3], al[3]);
            split2(b00, bh_[0], bl_[0]);
            split2(b10, bh_[1], bl_[1]);
            split2(b01, bh_[2], bl_[2]);
            split2(b11, bh_[3], bl_[3]);

            // ---- V fragments loaded ONCE, feed both q-tiles ----
#pragma unroll
            for (int et2 = 0; et2 < 4; et2++) {
                u32 off = (u32)(et2*16*VDP*4) + (u32)(ks*32) + vb_off;
                u32 Vh[4], Vl[4];
                ldsm4(Vh, vh_base + off);
                ldsm4(Vl, vl_base + off);
#pragma unroll
                for (int sub = 0; sub < 2; sub++) {
                    int nt = et2*2 + sub;
                    u32 v0 = Vh[sub*2], v1 = Vh[sub*2 + 1];
                    u32 u0 = Vl[sub*2], u1 = Vl[sub*2 + 1];
                    mma_bf(acc[0][nt], ah, v0, v1);
                    mma_bf(acc[0][nt], ah, u0, u1);
                    mma_bf(acc[0][nt], al, v0, v1);
                    mma_bf(acc[1][nt], bh_, v0, v1);
                    mma_bf(acc[1][nt], bh_, u0, u1);
                    mma_bf(acc[1][nt], bl_, v0, v1);
                }
            }
        }
    }

#pragma unroll
    for (int qt = 0; qt < 2; qt++) {
        size_t hb = (size_t)bhid*SS + q0 + qt*128 + w*16;
#pragma unroll
        for (int nt = 0; nt < 8; nt++) {
            int e = nt*8 + 2*tg;
            *(float2*)&g_heads[(hb + gid    )*DKK + e] = make_float2(acc[qt][nt][0], acc[qt][nt][1]);
            *(float2*)&g_heads[(hb + gid + 8)*DKK + e] = make_float2(acc[qt][nt][2], acc[qt][nt][3]);
        }
    }
}

// =====================================================================
// Kernel 5: head-average + output projection.
// =====================================================================
#define SMEM3_FLOATS (64*68 + 64*260)

__global__ __launch_bounds__(256) void outproj_kernel(
    const float* __restrict__ Wh, float* __restrict__ out)
{
    extern __shared__ float sm[];
    float* AvT = sm;             // [e][s] 64x68
    float* WhT = sm + 64*68;     // [e][dm] 64x260

    int s0 = blockIdx.x * 64;
    int tid = threadIdx.x;

#pragma unroll
    for (int i = 0; i < 16; i++) {
        int idx = tid + i*256;
        int sl = idx >> 6, e = idx & 63;
        int gr = s0 + sl;
        int bb = gr >> 11, s = gr & (SS-1);
        size_t base = ((size_t)bb*NH*SS + s)*DKK + e;
        float sum = g_heads[base]
                  + g_heads[base + (size_t)SS*DKK]
                  + g_heads[base + (size_t)2*SS*DKK]
                  + g_heads[base + (size_t)3*SS*DKK];
        AvT[e*68 + sl] = 0.25f * sum;
    }
#pragma unroll
    for (int i = 0; i < 64; i++) {
        int idx = tid + i*256;
        int dm = idx >> 6, e = idx & 63;
        WhT[e*260 + dm] = Wh[dm*DKK + e];
    }
    __syncthreads();

    int ts = tid >> 5;
    int tc = tid & 31;
    float acc[8][8];
#pragma unroll
    for (int i = 0; i < 8; i++)
#pragma unroll
        for (int j = 0; j < 8; j++) acc[i][j] = 0.0f;

#pragma unroll 8
    for (int e = 0; e < 64; e++) {
        float4 a0 = *(float4*)(AvT + e*68 + ts*8);
        float4 a1 = *(float4*)(AvT + e*68 + ts*8 + 4);
        float4 w0 = *(float4*)(WhT + e*260 + tc*8);
        float4 w1 = *(float4*)(WhT + e*260 + tc*8 + 4);
        float a[8] = {a0.x,a0.y,a0.z,a0.w,a1.x,a1.y,a1.z,a1.w};
        float wv[8] = {w0.x,w0.y,w0.z,w0.w,w1.x,w1.y,w1.z,w1.w};
#pragma unroll
        for (int i = 0; i < 8; i++)
#pragma unroll
            for (int j = 0; j < 8; j++) acc[i][j] = fmaf(a[i], wv[j], acc[i][j]);
    }
#pragma unroll
    for (int i = 0; i < 8; i++) {
        int gr = s0 + ts*8 + i;
        float4 o0 = make_float4(acc[i][0], acc[i][1], acc[i][2], acc[i][3]);
        float4 o1 = make_float4(acc[i][4], acc[i][5], acc[i][6], acc[i][7]);
        *(float4*)(out + (size_t)gr*DM + tc*8)     = o0;
        *(float4*)(out + (size_t)gr*DM + tc*8 + 4) = o1;
    }
}

// =====================================================================
extern "C" void kernel_launch(void* const* d_in, const int* in_sizes, int n_in,
                              void* d_out, int out_size)
{
    const float* q  = (const float*)d_in[0];
    const float* k  = (const float*)d_in[1];
    const float* v  = (const float*)d_in[2];
    const float* Wq = (const float*)d_in[3];
    const float* bq = (const float*)d_in[4];
    const float* Wk = (const float*)d_in[5];
    const float* bk = (const float*)d_in[6];
    const float* Wv = (const float*)d_in[7];
    const float* bv = (const float*)d_in[8];
    const float* Wh = (const float*)d_in[9];

    float* out  = (float*)d_out;                       // [B,S,DM]
    float* attn = out + (size_t)BB*SS*DM;              // [B,S,H,S]

    cudaFuncSetAttribute(proj_kernel, cudaFuncAttributeMaxDynamicSharedMemorySize,
                         PROJ_SMEM);
    cudaFuncSetAttribute(scores_kernel, cudaFuncAttributeMaxDynamicSharedMemorySize,
                         SCORES_SMEM);
    cudaFuncSetAttribute(pv_kernel, cudaFuncAttributeMaxDynamicSharedMemorySize,
                         PV_SMEM);
    cudaFuncSetAttribute(outproj_kernel, cudaFuncAttributeMaxDynamicSharedMemorySize,
                         SMEM3_FLOATS * sizeof(float));

    proj_kernel<<<dim3(NROWS/128, 9), 256, PROJ_SMEM>>>(q, k, v, Wq, bq, Wk, bk, Wv, bv);
    repack_qk_kernel<<<dim3(QKPAIRS/256, 2), 256>>>();
    repack_v_kernel<<<VTP/256, 256>>>();
    scores_kernel<<<dim3(4, 16, 32), 256, SCORES_SMEM>>>(attn);
    merge_kernel<<<NATTN/64, 256>>>();
    pv_kernel<<<dim3(8, 32), 256, PV_SMEM>>>(attn);
    outproj_kernel<<<NROWS/64, 256, SMEM3_FLOATS * sizeof(float)>>>(Wh, out);
}

// round 16
// speedup vs baseline: 1.6544x; 1.6544x over previous
#include <cuda_runtime.h>
#include <cuda_bf16.h>
#include <math.h>

typedef unsigned long long ull;
typedef unsigned int u32;

#define BB 8
#define SS 2048
#define DM 256
#define NH 4
#define DKK 64
#define NROWS (BB*SS)   // 16384

// ---- scratch (static device, no allocations) ----
__device__ float g_vs[BB*SS*DKK];
__device__ float g_heads[BB*NH*SS*DKK];
#define QKPAIRS (BB*NH*SS*32)            // 2,097,152
__device__ u32 g_qhi[QKPAIRS];
__device__ u32 g_qlo[QKPAIRS];
__device__ u32 g_khi[QKPAIRS];
__device__ u32 g_klo[QKPAIRS];
#define VTP (BB*DKK*(SS/2))              // 524,288
__device__ u32 g_vthi[VTP];
__device__ u32 g_vtlo[VTP];
#define NATTN (NROWS*NH)                 // 65536 attn rows
__device__ float2 g_part[NATTN*16];      // per (row, ktile): (max, expsum)
__device__ float2 g_stats[NATTN];        // per row [bh*SS+s]: (max, 1/sum)

// ---- bf16 helpers ----
__device__ __forceinline__ u32 bf2(float lo, float hi) {
    u32 r; asm("cvt.rn.bf16x2.f32 %0, %1, %2;" : "=r"(r) : "f"(hi), "f"(lo)); return r;
}
__device__ __forceinline__ float bflo(u32 p) { return __uint_as_float(p << 16); }
__device__ __forceinline__ float bfhi(u32 p) { return __uint_as_float(p & 0xffff0000u); }
__device__ __forceinline__ void split2(float2 p, u32& hi, u32& lo) {
    hi = bf2(p.x, p.y);
    lo = bf2(p.x - bflo(hi), p.y - bfhi(hi));
}

// ---- bf16 mma m16n8k16, fp32 accumulate ----
__device__ __forceinline__ void mma_bf(float* c, const u32* a, u32 b0, u32 b1) {
    asm volatile("mma.sync.aligned.m16n8k16.row.col.f32.bf16.bf16.f32 "
        "{%0,%1,%2,%3}, {%4,%5,%6,%7}, {%8,%9}, {%0,%1,%2,%3};"
        : "+f"(c[0]), "+f"(c[1]), "+f"(c[2]), "+f"(c[3])
        : "r"(a[0]), "r"(a[1]), "r"(a[2]), "r"(a[3]), "r"(b0), "r"(b1));
}

// ---- ldmatrix x4 ----
__device__ __forceinline__ void ldsm4(u32* r, u32 addr) {
    asm volatile("ldmatrix.sync.aligned.m8n8.x4.shared.b16 {%0,%1,%2,%3}, [%4];"
        : "=r"(r[0]), "=r"(r[1]), "=r"(r[2]), "=r"(r[3]) : "r"(addr));
}
__device__ __forceinline__ u32 smem_u32(const void* p) {
    return (u32)__cvta_generic_to_shared(p);
}

// =====================================================================
// Kernel 1: projections via bf16 3-pass mma. grid(128, 9), blk 256.
//   q/k results written DIRECTLY as bf16 hi/lo planes (no fp32, no
//   repack pass). v written fp32 (repack_v needs the transpose).
// =====================================================================
#define PJP 36
#define PROJ_SMEM ((2*128*PJP + 2*64*PJP)*4)   // 55,296 B

__global__ __launch_bounds__(256, 2) void proj_kernel(
    const float* __restrict__ qin, const float* __restrict__ kin,
    const float* __restrict__ vin,
    const float* __restrict__ Wq, const float* __restrict__ bq,
    const float* __restrict__ Wk, const float* __restrict__ bk,
    const float* __restrict__ Wv, const float* __restrict__ bv)
{
    extern __shared__ u32 smu[];
    u32* AH = smu;                 // [128][36]
    u32* AL = AH + 128*PJP;        // [128][36]
    u32* WH = AL + 128*PJP;        // [64][36]
    u32* WL = WH + 64*PJP;         // [64][36]

    int p = blockIdx.y;
    const float *A, *W, *bias;
    float scale; int h = 0;
    u32 *dsthi = 0, *dstlo = 0;
    if (p < 4)      { h = p;   A = qin; W = Wq + h*DKK*DM; bias = bq + h*DKK; scale = 0.125f; dsthi = g_qhi; dstlo = g_qlo; }
    else if (p < 8) { h = p-4; A = kin; W = Wk + h*DKK*DM; bias = bk + h*DKK; scale = 1.0f;   dsthi = g_khi; dstlo = g_klo; }
    else            {          A = vin; W = Wv;            bias = bv;         scale = 1.0f; }

    int row0 = blockIdx.x * 128;
    int tid  = threadIdx.x;
    int w    = tid >> 5;
    int lane = tid & 31;
    int gid  = lane >> 2;
    int tg   = lane & 3;

    u32 ah_base = smem_u32(AH), al_base = smem_u32(AL);
    u32 wh_base = smem_u32(WH), wl_base = smem_u32(WL);
    u32 a_off = ((u32)((lane & 15)*PJP) + (u32)((lane >> 4)*4)) * 4;
    u32 b_off = ((u32)(((lane & 7) + ((lane >> 4) << 3))*PJP) + (u32)(((lane >> 3) & 1)*4)) * 4;

    float acc[8][4];
#pragma unroll
    for (int nt = 0; nt < 8; nt++)
#pragma unroll
        for (int j = 0; j < 4; j++) acc[nt][j] = 0.0f;

    for (int d0 = 0; d0 < DM; d0 += 64) {
        __syncthreads();
#pragma unroll
        for (int i = 0; i < 8; i++) {
            int f4 = tid + i*256;
            int r = f4 >> 4, c = f4 & 15;
            float4 v = *(const float4*)(A + (size_t)(row0 + r)*DM + d0 + c*4);
            u32 h0, l0, h1, l1;
            split2(make_float2(v.x, v.y), h0, l0);
            split2(make_float2(v.z, v.w), h1, l1);
            AH[r*PJP + 2*c]     = h0;
            AH[r*PJP + 2*c + 1] = h1;
            AL[r*PJP + 2*c]     = l0;
            AL[r*PJP + 2*c + 1] = l1;
        }
#pragma unroll
        for (int i = 0; i < 4; i++) {
            int f4 = tid + i*256;
            int e = f4 >> 4, c = f4 & 15;
            float4 v = *(const float4*)(W + (size_t)e*DM + d0 + c*4);
            u32 h0, l0, h1, l1;
            split2(make_float2(v.x, v.y), h0, l0);
            split2(make_float2(v.z, v.w), h1, l1);
            WH[e*PJP + 2*c]     = h0;
            WH[e*PJP + 2*c + 1] = h1;
            WL[e*PJP + 2*c]     = l0;
            WL[e*PJP + 2*c + 1] = l1;
        }
        __syncthreads();

#pragma unroll
        for (int ks = 0; ks < 4; ks++) {
            u32 Ah[4], Al[4];
            u32 aoff = (u32)(w*16*PJP*4) + (u32)(ks*32) + a_off;
            ldsm4(Ah, ah_base + aoff);
            ldsm4(Al, al_base + aoff);
            u32 Bh[4][4], Bl[4][4];
#pragma unroll
            for (int et2 = 0; et2 < 4; et2++) {
                u32 off = (u32)(et2*16*PJP*4) + (u32)(ks*32) + b_off;
                ldsm4(Bh[et2], wh_base + off);
                ldsm4(Bl[et2], wl_base + off);
            }
#pragma unroll
            for (int nt = 0; nt < 8; nt++) {
                u32 b0 = Bh[nt>>1][(nt&1)*2], b1 = Bh[nt>>1][(nt&1)*2 + 1];
                u32 c0 = Bl[nt>>1][(nt&1)*2], c1 = Bl[nt>>1][(nt&1)*2 + 1];
                mma_bf(acc[nt], Ah, b0, b1);
                mma_bf(acc[nt], Ah, c0, c1);
                mma_bf(acc[nt], Al, b0, b1);
            }
        }
    }

    // epilogue: bias + scale; q/k -> bf16 hi/lo planes, v -> fp32
    int r0 = row0 + w*16 + gid;
#pragma unroll
    for (int nt = 0; nt < 8; nt++) {
        int e0 = nt*8 + 2*tg;
        float2 bv2 = *(const float2*)&bias[e0];
#pragma unroll
        for (int half = 0; half < 2; half++) {
            int gr = r0 + half*8;
            int bb = gr >> 11;
            int s  = gr & (SS-1);
            float o0 = (acc[nt][half*2 + 0] + bv2.x) * scale;
            float o1 = (acc[nt][half*2 + 1] + bv2.y) * scale;
            if (p < 8) {
                size_t base32 = ((size_t)(bb*NH + h)*SS + s)*32 + (e0 >> 1);
                u32 hi, lo; split2(make_float2(o0, o1), hi, lo);
                dsthi[base32] = hi;
                dstlo[base32] = lo;
            } else {
                *(float2*)&g_vs[(size_t)gr*DKK + e0] = make_float2(o0, o1);
            }
        }
    }
}

// =====================================================================
// Kernel 1c: V -> transposed bf16x2 hi/lo. grid(2048), blk 256.
// =====================================================================
__global__ __launch_bounds__(256) void repack_v_kernel()
{
    int t = blockIdx.x * 256 + threadIdx.x;
    int b  = t >> 16;
    int r  = t & 65535;
    int e  = r >> 10;
    int sp = r & 1023;
    float v0 = g_vs[((size_t)b*SS + 2*sp    )*DKK + e];
    float v1 = g_vs[((size_t)b*SS + 2*sp + 1)*DKK + e];
    u32 hi, lo; split2(make_float2(v0, v1), hi, lo);
    g_vthi[t] = hi; g_vtlo[t] = lo;
}

// =====================================================================
// Kernel 2: scores GEMM v4 (round-14 WINNER, unchanged).
//   grid(4 kgroup, 16 qtile, 32 bh), blk 256.
// =====================================================================
#define SCP 36
#define SCORES_SMEM (4*128*SCP*4)

__global__ __launch_bounds__(256, 2) void scores_kernel(float* __restrict__ attn)
{
    extern __shared__ u32 smu[];
    u32* QH = smu;
    u32* QL = QH + 128*SCP;
    u32* KH = QL + 128*SCP;
    u32* KL = KH + 128*SCP;
    float2* spart = (float2*)KH;         // alias on KH (dead after mainloop)

    int bhid = blockIdx.z;
    int b = bhid >> 2, h = bhid & 3;
    int q0 = blockIdx.y * 128;
    int kg = blockIdx.x;                 // 0..3, 4 ktiles each
    int tid  = threadIdx.x;
    int w    = tid >> 5;
    int lane = tid & 31;
    int gid  = lane >> 2;
    int tg   = lane & 3;

    const u32* qhi = g_qhi + (size_t)bhid*SS*32;
    const u32* qlo = g_qlo + (size_t)bhid*SS*32;
    const u32* khi = g_khi + (size_t)bhid*SS*32;
    const u32* klo = g_klo + (size_t)bhid*SS*32;

    // ---- stage Q planes ONCE ----
#pragma unroll
    for (int i = 0; i < 4; i++) {
        int f4 = tid + i*256;
        int r = f4 >> 3, fo = (f4 & 7) * 4;
        *(uint4*)&QH[r*SCP + fo] = *(const uint4*)&qhi[(size_t)(q0 + r)*32 + fo];
        *(uint4*)&QL[r*SCP + fo] = *(const uint4*)&qlo[(size_t)(q0 + r)*32 + fo];
    }

    int wq = w >> 2;   // 0..1 : 64 q rows
    int wk = w & 3;    // 0..3 : 32 k cols

    u32 qh_base = smem_u32(QH), ql_base = smem_u32(QL);
    u32 kh_base = smem_u32(KH), kl_base = smem_u32(KL);
    u32 a_off = ((u32)((lane & 15)*SCP) + (u32)((lane >> 4)*4)) * 4;
    u32 b_off = ((u32)(((lane & 7) + ((lane >> 4) << 3))*SCP) + (u32)(((lane >> 3) & 1)*4)) * 4;

    for (int kt2 = 0; kt2 < 4; kt2++) {
        int ktile = kg*4 + kt2;
        int k0 = ktile * 128;

        __syncthreads();   // Q staged (iter 0) / prior spart reads done
#pragma unroll
        for (int i = 0; i < 4; i++) {
            int f4 = tid + i*256;
            int r = f4 >> 3, fo = (f4 & 7) * 4;
            *(uint4*)&KH[r*SCP + fo] = *(const uint4*)&khi[(size_t)(k0 + r)*32 + fo];
            *(uint4*)&KL[r*SCP + fo] = *(const uint4*)&klo[(size_t)(k0 + r)*32 + fo];
        }
        __syncthreads();

        float acc[4][4][4];
#pragma unroll
        for (int mt = 0; mt < 4; mt++)
#pragma unroll
            for (int nt = 0; nt < 4; nt++)
#pragma unroll
                for (int j = 0; j < 4; j++) acc[mt][nt][j] = 0.0f;

#pragma unroll
        for (int ks = 0; ks < 4; ks++) {
            u32 Bh[2][4], Bl[2][4];
#pragma unroll
            for (int nt2 = 0; nt2 < 2; nt2++) {
                u32 off = (u32)((wk*32 + nt2*16)*SCP*4) + (u32)(ks*32) + b_off;
                ldsm4(Bh[nt2], kh_base + off);
                ldsm4(Bl[nt2], kl_base + off);
            }
#pragma unroll
            for (int mt = 0; mt < 4; mt++) {
                u32 Ah[4], Al[4];
                u32 off = (u32)((wq*64 + mt*16)*SCP*4) + (u32)(ks*32) + a_off;
                ldsm4(Ah, qh_base + off);
                ldsm4(Al, ql_base + off);
#pragma unroll
                for (int nt = 0; nt < 4; nt++) {
                    u32 b0h = Bh[nt>>1][(nt&1)*2], b1h = Bh[nt>>1][(nt&1)*2 + 1];
                    u32 b0l = Bl[nt>>1][(nt&1)*2], b1l = Bl[nt>>1][(nt&1)*2 + 1];
                    mma_bf(acc[mt][nt], Ah, b0h, b1h);
                    mma_bf(acc[mt][nt], Ah, b0l, b1l);
                    mma_bf(acc[mt][nt], Al, b0h, b1h);
                }
            }
        }

        // epilogue A: raw scores -> attn (register scatter, proven fine)
        float* ab = attn + (((size_t)b*SS + q0)*NH + h)*SS + k0;
#pragma unroll
        for (int mt = 0; mt < 4; mt++) {
            int r = wq*64 + mt*16 + gid;
#pragma unroll
            for (int nt = 0; nt < 4; nt++) {
                int c = wk*32 + nt*8 + 2*tg;
                *(float2*)&ab[(size_t)r*NH*SS + c]       = make_float2(acc[mt][nt][0], acc[mt][nt][1]);
                *(float2*)&ab[(size_t)(r + 8)*NH*SS + c] = make_float2(acc[mt][nt][2], acc[mt][nt][3]);
            }
        }

        // epilogue B: per-(row, ktile) softmax partials into spart (on KH)
        __syncthreads();   // KH ldsm reads complete
#pragma unroll
        for (int mt = 0; mt < 4; mt++) {
            float m0 = -1e30f, m1 = -1e30f;
#pragma unroll
            for (int nt = 0; nt < 4; nt++) {
                m0 = fmaxf(m0, fmaxf(acc[mt][nt][0], acc[mt][nt][1]));
                m1 = fmaxf(m1, fmaxf(acc[mt][nt][2], acc[mt][nt][3]));
            }
            float s0 = 0.f, s1 = 0.f;
#pragma unroll
            for (int nt = 0; nt < 4; nt++) {
                s0 += __expf(acc[mt][nt][0] - m0) + __expf(acc[mt][nt][1] - m0);
                s1 += __expf(acc[mt][nt][2] - m1) + __expf(acc[mt][nt][3] - m1);
            }
#pragma unroll
            for (int off = 1; off <= 2; off <<= 1) {
                float mo0 = __shfl_xor_sync(0xffffffffu, m0, off);
                float so0 = __shfl_xor_sync(0xffffffffu, s0, off);
                float mo1 = __shfl_xor_sync(0xffffffffu, m1, off);
                float so1 = __shfl_xor_sync(0xffffffffu, s1, off);
                float nm0 = fmaxf(m0, mo0);
                s0 = s0*__expf(m0 - nm0) + so0*__expf(mo0 - nm0); m0 = nm0;
                float nm1 = fmaxf(m1, mo1);
                s1 = s1*__expf(m1 - nm1) + so1*__expf(mo1 - nm1); m1 = nm1;
            }
            if (tg == 0) {
                int r0 = wq*64 + mt*16 + gid;
                spart[r0*4 + wk]       = make_float2(m0, s0);
                spart[(r0 + 8)*4 + wk] = make_float2(m1, s1);
            }
        }
        __syncthreads();
        if (tid < 128) {
            float2 p0 = spart[tid*4 + 0];
            float2 p1 = spart[tid*4 + 1];
            float2 p2 = spart[tid*4 + 2];
            float2 p3 = spart[tid*4 + 3];
            float m = fmaxf(fmaxf(p0.x, p1.x), fmaxf(p2.x, p3.x));
            float s = p0.y*__expf(p0.x - m) + p1.y*__expf(p1.x - m)
                    + p2.y*__expf(p2.x - m) + p3.y*__expf(p3.x - m);
            g_part[((size_t)bhid*SS + q0 + tid)*16 + ktile] = make_float2(m, s);
        }
    }
}

// =====================================================================
// Kernel 3: merge partials -> g_stats. grid(1024), blk 256, smem-staged.
// =====================================================================
__global__ __launch_bounds__(256) void merge_kernel()
{
    __shared__ float2 sp[64*16];
    int tid = threadIdx.x;
    const uint4* src = (const uint4*)(g_part + (size_t)blockIdx.x*64*16);
    uint4* d = (uint4*)sp;
    d[tid]       = src[tid];
    d[tid + 256] = src[tid + 256];
    __syncthreads();
    if (tid < 64) {
        const float2* p = &sp[tid*16];
        float m = -1e30f;
#pragma unroll
        for (int i = 0; i < 16; i++) m = fmaxf(m, p[i].x);
        float s = 0.f;
#pragma unroll
        for (int i = 0; i < 16; i++) s += p[i].y * __expf(p[i].x - m);
        g_stats[blockIdx.x*64 + tid] = make_float2(m, 1.0f / s);
    }
}

// =====================================================================
// Kernel 4: PV (round-8 form, PROVEN) + in-place normalize.
//   grid(16,32), blk 256.
// =====================================================================
#define VDP 68
#define PV_SMEM (2*64*VDP*4)

__global__ __launch_bounds__(256, 2) void pv_kernel(float* __restrict__ attn)
{
    extern __shared__ u32 smu[];
    u32* VH = smu;
    u32* VL = VH + 64*VDP;

    int bhid = blockIdx.y;
    int b = bhid >> 2, h = bhid & 3;
    int q0 = blockIdx.x * 128;
    int tid  = threadIdx.x;
    int w    = tid >> 5;
    int lane = tid & 31;
    int gid  = lane >> 2;
    int tg   = lane & 3;

    const u32* vh = g_vthi + (size_t)b*DKK*1024;
    const u32* vl = g_vtlo + (size_t)b*DKK*1024;

    int qa = q0 + w*16 + gid;
    float2 st0 = g_stats[(size_t)bhid*SS + qa];
    float2 st1 = g_stats[(size_t)bhid*SS + qa + 8];
    float m0 = st0.x, i0 = st0.y;
    float m1 = st1.x, i1 = st1.y;

    float* rlo = attn + (((size_t)b*SS + qa    )*NH + h)*SS;
    float* rhi = attn + (((size_t)b*SS + qa + 8)*NH + h)*SS;

    u32 vh_base = smem_u32(VH), vl_base = smem_u32(VL);
    u32 vb_off = ((u32)(((lane & 7) + ((lane >> 4) << 3))*VDP) + (u32)(((lane >> 3) & 1)*4)) * 4;

    float acc[8][4];
#pragma unroll
    for (int nt = 0; nt < 8; nt++)
#pragma unroll
        for (int j = 0; j < 4; j++) acc[nt][j] = 0.0f;

    for (int kt = 0; kt < 16; kt++) {
        int k0 = kt * 128;
        __syncthreads();
#pragma unroll
        for (int i = 0; i < 4; i++) {
            int f4 = tid + i*256;
            int e = f4 >> 4, fo = (f4 & 15) * 4;
            *(uint4*)&VH[e*VDP + fo] = *(const uint4*)&vh[(size_t)e*1024 + k0/2 + fo];
            *(uint4*)&VL[e*VDP + fo] = *(const uint4*)&vl[(size_t)e*1024 + k0/2 + fo];
        }
        __syncthreads();

#pragma unroll
        for (int ks = 0; ks < 8; ks++) {
            int c = k0 + ks*16 + 2*tg;
            float2 p00 = *(float2*)&rlo[c];
            float2 p10 = *(float2*)&rhi[c];
            float2 p01 = *(float2*)&rlo[c + 8];
            float2 p11 = *(float2*)&rhi[c + 8];
            p00.x = __expf(p00.x - m0) * i0;  p00.y = __expf(p00.y - m0) * i0;
            p10.x = __expf(p10.x - m1) * i1;  p10.y = __expf(p10.y - m1) * i1;
            p01.x = __expf(p01.x - m0) * i0;  p01.y = __expf(p01.y - m0) * i0;
            p11.x = __expf(p11.x - m1) * i1;  p11.y = __expf(p11.y - m1) * i1;
            *(float2*)&rlo[c]     = p00;
            *(float2*)&rhi[c]     = p10;
            *(float2*)&rlo[c + 8] = p01;
            *(float2*)&rhi[c + 8] = p11;
            u32 ah[4], al[4];
            split2(p00, ah[0], al[0]);
            split2(p10, ah[1], al[1]);
            split2(p01, ah[2], al[2]);
            split2(p11, ah[3], al[3]);

            u32 Bh[4][4], Bl[4][4];
#pragma unroll
            for (int et2 = 0; et2 < 4; et2++) {
                u32 off = (u32)(et2*16*VDP*4) + (u32)(ks*32) + vb_off;
                ldsm4(Bh[et2], vh_base + off);
                ldsm4(Bl[et2], vl_base + off);
            }
#pragma unroll
            for (int nt = 0; nt < 8; nt++) {
                u32 b0 = Bh[nt>>1][(nt&1)*2], b1 = Bh[nt>>1][(nt&1)*2 + 1];
                u32 c0 = Bl[nt>>1][(nt&1)*2], c1 = Bl[nt>>1][(nt&1)*2 + 1];
                mma_bf(acc[nt], ah, b0, b1);
                mma_bf(acc[nt], ah, c0, c1);
                mma_bf(acc[nt], al, b0, b1);
            }
        }
    }

    size_t hb = (size_t)bhid*SS + q0 + w*16;
#pragma unroll
    for (int nt = 0; nt < 8; nt++) {
        int e = nt*8 + 2*tg;
        *(float2*)&g_heads[(hb + gid    )*DKK + e] = make_float2(acc[nt][0], acc[nt][1]);
        *(float2*)&g_heads[(hb + gid + 8)*DKK + e] = make_float2(acc[nt][2], acc[nt][3]);
    }
}

// =====================================================================
// Kernel 5: head-average + output projection.
// =====================================================================
#define SMEM3_FLOATS (64*68 + 64*260)

__global__ __launch_bounds__(256) void outproj_kernel(
    const float* __restrict__ Wh, float* __restrict__ out)
{
    extern __shared__ float sm[];
    float* AvT = sm;             // [e][s] 64x68
    float* WhT = sm + 64*68;     // [e][dm] 64x260

    int s0 = blockIdx.x * 64;
    int tid = threadIdx.x;

#pragma unroll
    for (int i = 0; i < 16; i++) {
        int idx = tid + i*256;
        int sl = idx >> 6, e = idx & 63;
        int gr = s0 + sl;
        int bb = gr >> 11, s = gr & (SS-1);
        size_t base = ((size_t)bb*NH*SS + s)*DKK + e;
        float sum = g_heads[base]
                  + g_heads[base + (size_t)SS*DKK]
                  + g_heads[base + (size_t)2*SS*DKK]
                  + g_heads[base + (size_t)3*SS*DKK];
        AvT[e*68 + sl] = 0.25f * sum;
    }
#pragma unroll
    for (int i = 0; i < 64; i++) {
        int idx = tid + i*256;
        int dm = idx >> 6, e = idx & 63;
        WhT[e*260 + dm] = Wh[dm*DKK + e];
    }
    __syncthreads();

    int ts = tid >> 5;
    int tc = tid & 31;
    float acc[8][8];
#pragma unroll
    for (int i = 0; i < 8; i++)
#pragma unroll
        for (int j = 0; j < 8; j++) acc[i][j] = 0.0f;

#pragma unroll 8
    for (int e = 0; e < 64; e++) {
        float4 a0 = *(float4*)(AvT + e*68 + ts*8);
        float4 a1 = *(float4*)(AvT + e*68 + ts*8 + 4);
        float4 w0 = *(float4*)(WhT + e*260 + tc*8);
        float4 w1 = *(float4*)(WhT + e*260 + tc*8 + 4);
        float a[8] = {a0.x,a0.y,a0.z,a0.w,a1.x,a1.y,a1.z,a1.w};
        float wv[8] = {w0.x,w0.y,w0.z,w0.w,w1.x,w1.y,w1.z,w1.w};
#pragma unroll
        for (int i = 0; i < 8; i++)
#pragma unroll
            for (int j = 0; j < 8; j++) acc[i][j] = fmaf(a[i], wv[j], acc[i][j]);
    }
#pragma unroll
    for (int i = 0; i < 8; i++) {
        int gr = s0 + ts*8 + i;
        float4 o0 = make_float4(acc[i][0], acc[i][1], acc[i][2], acc[i][3]);
        float4 o1 = make_float4(acc[i][4], acc[i][5], acc[i][6], acc[i][7]);
        *(float4*)(out + (size_t)gr*DM + tc*8)     = o0;
        *(float4*)(out + (size_t)gr*DM + tc*8 + 4) = o1;
    }
}

// =====================================================================
extern "C" void kernel_launch(void* const* d_in, const int* in_sizes, int n_in,
                              void* d_out, int out_size)
{
    const float* q  = (const float*)d_in[0];
    const float* k  = (const float*)d_in[1];
    const float* v  = (const float*)d_in[2];
    const float* Wq = (const float*)d_in[3];
    const float* bq = (const float*)d_in[4];
    const float* Wk = (const float*)d_in[5];
    const float* bk = (const float*)d_in[6];
    const float* Wv = (const float*)d_in[7];
    const float* bv = (const float*)d_in[8];
    const float* Wh = (const float*)d_in[9];

    float* out  = (float*)d_out;                       // [B,S,DM]
    float* attn = out + (size_t)BB*SS*DM;              // [B,S,H,S]

    cudaFuncSetAttribute(proj_kernel, cudaFuncAttributeMaxDynamicSharedMemorySize,
                         PROJ_SMEM);
    cudaFuncSetAttribute(scores_kernel, cudaFuncAttributeMaxDynamicSharedMemorySize,
                         SCORES_SMEM);
    cudaFuncSetAttribute(pv_kernel, cudaFuncAttributeMaxDynamicSharedMemorySize,
                         PV_SMEM);
    cudaFuncSetAttribute(outproj_kernel, cudaFuncAttributeMaxDynamicSharedMemorySize,
                         SMEM3_FLOATS * sizeof(float));

    proj_kernel<<<dim3(NROWS/128, 9), 256, PROJ_SMEM>>>(q, k, v, Wq, bq, Wk, bk, Wv, bv);
    repack_v_kernel<<<VTP/256, 256>>>();
    scores_kernel<<<dim3(4, 16, 32), 256, SCORES_SMEM>>>(attn);
    merge_kernel<<<NATTN/64, 256>>>();
    pv_kernel<<<dim3(16, 32), 256, PV_SMEM>>>(attn);
    outproj_kernel<<<NROWS/64, 256, SMEM3_FLOATS * sizeof(float)>>>(Wh, out);
}